// round 8
// baseline (speedup 1.0000x reference)
#include <cuda_runtime.h>
#include <math.h>
#include <stdint.h>

#define Bn 4
#define Tn 2048
#define Cn 1024
#define Hn 16
#define Dn 64
#define NT (Bn * Tn)
#define C3 (3 * Cn)

__device__ float g_q[(size_t)Bn * Hn * Tn * Dn];
__device__ float g_k[(size_t)Bn * Hn * Tn * Dn];
__device__ float g_v[(size_t)Bn * Hn * Tn * Dn];
__device__ float g_y[(size_t)NT * Cn];
// pre-rounded (tf32-in-fp32) copies so the GEMM mainloop can use raw cp.async
__device__ float g_x[(size_t)NT * Cn];
__device__ float g_wqkv[(size_t)Cn * C3];
__device__ float g_wproj[(size_t)Cn * Cn];

// ---------------------------------------------------------------------------
// helpers
// ---------------------------------------------------------------------------
__device__ __forceinline__ float f2tf(float x) {
    float y;
    asm("cvt.rna.tf32.f32 %0, %1;" : "=f"(y) : "f"(x));
    return y;
}

__device__ __forceinline__ float ex2(float x) {
    float y;
    asm("ex2.approx.f32 %0, %1;" : "=f"(y) : "f"(x));
    return y;
}

__device__ __forceinline__ void mma8(float d[4], const uint32_t a[4],
                                     const uint32_t b[2], const float c[4]) {
    asm volatile(
        "mma.sync.aligned.m16n8k8.row.col.f32.tf32.tf32.f32 "
        "{%0,%1,%2,%3}, {%4,%5,%6,%7}, {%8,%9}, {%10,%11,%12,%13};"
        : "=f"(d[0]), "=f"(d[1]), "=f"(d[2]), "=f"(d[3])
        : "r"(a[0]), "r"(a[1]), "r"(a[2]), "r"(a[3]),
          "r"(b[0]), "r"(b[1]),
          "f"(c[0]), "f"(c[1]), "f"(c[2]), "f"(c[3]));
}

__device__ __forceinline__ uint32_t smem_u32(const void* p) {
    return (uint32_t)__cvta_generic_to_shared(p);
}

#define CPA16(s, gp) \
    asm volatile("cp.async.cg.shared.global [%0], [%1], 16;" :: "r"(s), "l"(gp))

// ---------------------------------------------------------------------------
// Prepass: RNA-round fp32 -> tf32-in-fp32 into device globals.
// WHICH selects dst in device code (never pass __device__ symbols from host).
// ---------------------------------------------------------------------------
template <int WHICH>
__global__ void round_tf32(const float* __restrict__ src, int n4) {
    float* dst = (WHICH == 0) ? g_x : (WHICH == 1) ? g_wqkv : g_wproj;
    const int i = blockIdx.x * blockDim.x + threadIdx.x;
    if (i < n4) {
        float4 v = ((const float4*)src)[i];
        ((float4*)dst)[i] =
            make_float4(f2tf(v.x), f2tf(v.y), f2tf(v.z), f2tf(v.w));
    }
}

// ---------------------------------------------------------------------------
// GEMM v2: BM=256 BN=128 BK=16, 8 warps in 4x2, warp tile 64x64.
// Double-buffered smem fed by cp.async (inputs pre-rounded to tf32).
// MODE 0: A=g_x, W=g_wqkv, scatter epilogue -> g_q/g_k/g_v.
// MODE 1: A=g_y, W=g_wproj, out epilogue (+bias).
// Smem: As stride 20 (afr lanes -> words 20g+q mod 32, all distinct),
//       Bs stride 136 (8q+g, all distinct) -> conflict-free fragment loads.
// ---------------------------------------------------------------------------
#define GEMM_SMEM ((2 * 256 * 20 + 2 * 16 * 136) * 4)

template <int MODE>
__global__ __launch_bounds__(256, 1) void gemm_v2(const float* __restrict__ bias,
                                                  float* __restrict__ out) {
    const float* __restrict__ A = MODE ? (const float*)g_y : (const float*)g_x;
    const float* __restrict__ W = MODE ? (const float*)g_wproj : (const float*)g_wqkv;
    const int ldb = MODE ? Cn : C3;

    extern __shared__ float sm[];
    float* Asm = sm;                 // [2][256][20]
    float* Bsm = sm + 2 * 256 * 20;  // [2][16][136]

    const int tid = threadIdx.x;
    const int lane = tid & 31;
    const int warp = tid >> 5;
    const int warpM = warp >> 1;     // 0..3 -> 64-row slab
    const int warpN = warp & 1;      // 0..1 -> 64-col slab
    const int g = lane >> 2;
    const int q = lane & 3;

    const int rowBase = blockIdx.y * 256;
    const int colBase = blockIdx.x * 128;

    const int bRow = tid >> 4;          // 0..15
    const int bCol = (tid & 15) * 8;    // 0..120

    const float* agp = A + (size_t)(rowBase + tid) * Cn;        // 1 row/thread
    const float* bgp = W + (size_t)bRow * ldb + colBase + bCol;

    const uint32_t asBase = smem_u32(&Asm[tid * 20]);
    const uint32_t bsBase = smem_u32(&Bsm[bRow * 136 + bCol]);

    float acc[4][8][4] = {};

#define ISSUE_TILE(k0, buf)                                       \
    do {                                                          \
        const float* ag = agp + (k0);                             \
        const uint32_t as = asBase + (buf) * (5120 * 4);          \
        CPA16(as,      ag);                                       \
        CPA16(as + 16, ag + 4);                                   \
        CPA16(as + 32, ag + 8);                                   \
        CPA16(as + 48, ag + 12);                                  \
        const float* bg = bgp + (size_t)(k0) * ldb;               \
        const uint32_t bs = bsBase + (buf) * (2176 * 4);          \
        CPA16(bs,      bg);                                       \
        CPA16(bs + 16, bg + 4);                                   \
        asm volatile("cp.async.commit_group;");                   \
    } while (0)

    ISSUE_TILE(0, 0);

    for (int it = 0; it < 64; it++) {
        const int buf = it & 1;
        if (it < 63) {
            ISSUE_TILE((it + 1) * 16, buf ^ 1);
            asm volatile("cp.async.wait_group 1;");
        } else {
            asm volatile("cp.async.wait_group 0;");
        }
        __syncthreads();

        const float* Ab = &Asm[buf * 5120];
        const float* Bb = &Bsm[buf * 2176];
#pragma unroll
        for (int ks = 0; ks < 16; ks += 8) {
            uint32_t afr[4][4];
#pragma unroll
            for (int mt = 0; mt < 4; mt++) {
                const int r = warpM * 64 + mt * 16 + g;
                afr[mt][0] = __float_as_uint(Ab[r * 20 + ks + q]);
                afr[mt][1] = __float_as_uint(Ab[(r + 8) * 20 + ks + q]);
                afr[mt][2] = __float_as_uint(Ab[r * 20 + ks + q + 4]);
                afr[mt][3] = __float_as_uint(Ab[(r + 8) * 20 + ks + q + 4]);
            }
#pragma unroll
            for (int nt = 0; nt < 8; nt++) {
                const int c = warpN * 64 + nt * 8 + g;
                uint32_t b2[2];
                b2[0] = __float_as_uint(Bb[(ks + q) * 136 + c]);
                b2[1] = __float_as_uint(Bb[(ks + q + 4) * 136 + c]);
#pragma unroll
                for (int mt = 0; mt < 4; mt++)
                    mma8(acc[mt][nt], afr[mt], b2, acc[mt][nt]);
            }
        }
        __syncthreads();
    }

    // Epilogue
#pragma unroll
    for (int mt = 0; mt < 4; mt++) {
#pragma unroll
        for (int ih = 0; ih < 2; ih++) {
            const int m = rowBase + warpM * 64 + mt * 16 + g + ih * 8;
#pragma unroll
            for (int nt = 0; nt < 8; nt++) {
                const int n = colBase + warpN * 64 + nt * 8 + q * 2;
                const float v0 = acc[mt][nt][ih * 2 + 0] + bias[n];
                const float v1 = acc[mt][nt][ih * 2 + 1] + bias[n + 1];
                if (MODE == 1) {
                    *(float2*)&out[(size_t)m * Cn + n] = make_float2(v0, v1);
                } else {
                    const int which = n >> 10;       // 0=q 1=k 2=v
                    const int cc = n & 1023;
                    const int h = cc >> 6;
                    const int d = cc & 63;
                    const int b = m >> 11;
                    const int t = m & 2047;
                    float* dst = (which == 0) ? g_q : (which == 1) ? g_k : g_v;
                    *(float2*)&dst[(((size_t)b * Hn + h) * Tn + t) * Dn + d] =
                        make_float2(v0, v1);
                }
            }
        }
    }
#undef ISSUE_TILE
}

// ---------------------------------------------------------------------------
// Tensor-core flash attention (causal), unchanged from R7 except the epilogue
// writes f2tf-rounded values to g_y so the proj GEMM can cp.async it raw.
// ---------------------------------------------------------------------------
#define LKV 72
#define ATTN_SMEM ((2 * 64 * LKV + 4 * 16 * LKV) * 4)

__global__ __launch_bounds__(128, 3) void attn_tc() {
    extern __shared__ float smf[];
    float* Kn = smf;                    // [kv][d]  stride LKV
    float* Vs = smf + 64 * LKV;         // [kv][d]  stride LKV
    float* Pw = smf + 2 * 64 * LKV;     // per-warp [16][LKV]

    const int qt = blockIdx.x;
    const int bh = blockIdx.y;
    const int b = bh >> 4;
    const int h = bh & 15;

    const int tid = threadIdx.x;
    const int w = tid >> 5;
    const int lane = tid & 31;
    const int g = lane >> 2;
    const int q = lane & 3;

    const float qscale = 0.125f * 1.44269504f;
    const float* qg = g_q + ((size_t)bh * Tn + qt * 64 + w * 16) * Dn;
    uint32_t aQ[8][4];
#pragma unroll
    for (int ks = 0; ks < 8; ks++) {
        aQ[ks][0] = __float_as_uint(f2tf(qg[g * Dn + ks * 8 + q] * qscale));
        aQ[ks][1] = __float_as_uint(f2tf(qg[(g + 8) * Dn + ks * 8 + q] * qscale));
        aQ[ks][2] = __float_as_uint(f2tf(qg[g * Dn + ks * 8 + q + 4] * qscale));
        aQ[ks][3] = __float_as_uint(f2tf(qg[(g + 8) * Dn + ks * 8 + q + 4] * qscale));
    }

    float o[8][4] = {};
    float mrow[2] = {-INFINITY, -INFINITY};
    float lrow[2] = {0.0f, 0.0f};

    const float* kg0 = g_k + (size_t)bh * Tn * Dn;
    const float* vg0 = g_v + (size_t)bh * Tn * Dn;
    float* Pme = Pw + w * 16 * LKV;

    for (int j = 0; j <= qt; j++) {
        __syncthreads();
        const float* kg = kg0 + (size_t)j * 64 * Dn;
        const float* vg = vg0 + (size_t)j * 64 * Dn;
        for (int i = tid; i < 64 * 16; i += 128) {
            const int r = i >> 4;
            const int c = (i & 15) * 4;
            float4 k4 = *(const float4*)&kg[r * Dn + c];
            *(float4*)&Kn[r * LKV + c] =
                make_float4(f2tf(k4.x), f2tf(k4.y), f2tf(k4.z), f2tf(k4.w));
            float4 v4 = *(const float4*)&vg[r * Dn + c];
            *(float4*)&Vs[r * LKV + c] =
                make_float4(f2tf(v4.x), f2tf(v4.y), f2tf(v4.z), f2tf(v4.w));
        }
        __syncthreads();

        float s[8][4] = {};
#pragma unroll
        for (int ks = 0; ks < 8; ks++) {
            uint32_t bf[8][2];
#pragma unroll
            for (int nt = 0; nt < 8; nt++) {
                bf[nt][0] = __float_as_uint(Kn[(nt * 8 + g) * LKV + ks * 8 + q]);
                bf[nt][1] = __float_as_uint(Kn[(nt * 8 + g) * LKV + ks * 8 + q + 4]);
            }
#pragma unroll
            for (int nt = 0; nt < 8; nt++)
                mma8(s[nt], aQ[ks], bf[nt], s[nt]);
        }

        if (j == qt) {
            const int lr0 = w * 16 + g;
            const int lr1 = lr0 + 8;
#pragma unroll
            for (int nt = 0; nt < 8; nt++) {
                const int lc = nt * 8 + 2 * q;
                if (lc > lr0) s[nt][0] = -INFINITY;
                if (lc + 1 > lr0) s[nt][1] = -INFINITY;
                if (lc > lr1) s[nt][2] = -INFINITY;
                if (lc + 1 > lr1) s[nt][3] = -INFINITY;
            }
        }

#pragma unroll
        for (int r = 0; r < 2; r++) {
            float mx = mrow[r];
#pragma unroll
            for (int nt = 0; nt < 8; nt++)
                mx = fmaxf(mx, fmaxf(s[nt][2 * r], s[nt][2 * r + 1]));
            mx = fmaxf(mx, __shfl_xor_sync(0xffffffffu, mx, 1));
            mx = fmaxf(mx, __shfl_xor_sync(0xffffffffu, mx, 2));
            const float alpha = ex2(mrow[r] - mx);
            float sum = 0.0f;
#pragma unroll
            for (int nt = 0; nt < 8; nt++) {
                const float p0 = ex2(s[nt][2 * r] - mx);
                const float p1 = ex2(s[nt][2 * r + 1] - mx);
                s[nt][2 * r] = p0;
                s[nt][2 * r + 1] = p1;
                sum += p0 + p1;
                o[nt][2 * r] *= alpha;
                o[nt][2 * r + 1] *= alpha;
            }
            sum += __shfl_xor_sync(0xffffffffu, sum, 1);
            sum += __shfl_xor_sync(0xffffffffu, sum, 2);
            lrow[r] = lrow[r] * alpha + sum;
            mrow[r] = mx;
        }

#pragma unroll
        for (int nt = 0; nt < 8; nt++) {
            *(float2*)&Pme[g * LKV + nt * 8 + 2 * q] =
                make_float2(f2tf(s[nt][0]), f2tf(s[nt][1]));
            *(float2*)&Pme[(g + 8) * LKV + nt * 8 + 2 * q] =
                make_float2(f2tf(s[nt][2]), f2tf(s[nt][3]));
        }
        __syncwarp();

#pragma unroll
        for (int ks = 0; ks < 8; ks++) {
            uint32_t aP[4];
            aP[0] = __float_as_uint(Pme[g * LKV + ks * 8 + q]);
            aP[1] = __float_as_uint(Pme[(g + 8) * LKV + ks * 8 + q]);
            aP[2] = __float_as_uint(Pme[g * LKV + ks * 8 + q + 4]);
            aP[3] = __float_as_uint(Pme[(g + 8) * LKV + ks * 8 + q + 4]);
            uint32_t bf[8][2];
#pragma unroll
            for (int nt = 0; nt < 8; nt++) {
                bf[nt][0] = __float_as_uint(Vs[(ks * 8 + q) * LKV + nt * 8 + g]);
                bf[nt][1] = __float_as_uint(Vs[(ks * 8 + q + 4) * LKV + nt * 8 + g]);
            }
#pragma unroll
            for (int nt = 0; nt < 8; nt++)
                mma8(o[nt], aP, bf[nt], o[nt]);
        }
    }

    const float inv0 = 1.0f / lrow[0];
    const float inv1 = 1.0f / lrow[1];
    float* yg = g_y + ((size_t)b * Tn + qt * 64 + w * 16) * Cn + h * Dn;
#pragma unroll
    for (int nt = 0; nt < 8; nt++) {
        *(float2*)&yg[(size_t)g * Cn + nt * 8 + 2 * q] =
            make_float2(f2tf(o[nt][0] * inv0), f2tf(o[nt][1] * inv0));
        *(float2*)&yg[(size_t)(g + 8) * Cn + nt * 8 + 2 * q] =
            make_float2(f2tf(o[nt][2] * inv1), f2tf(o[nt][3] * inv1));
    }
}

// ---------------------------------------------------------------------------
extern "C" void kernel_launch(void* const* d_in, const int* in_sizes, int n_in,
                              void* d_out, int out_size) {
    const float* x      = (const float*)d_in[0];
    const float* w_qkv  = (const float*)d_in[1];
    const float* b_qkv  = (const float*)d_in[2];
    const float* w_proj = (const float*)d_in[3];
    const float* b_proj = (const float*)d_in[4];
    float* out = (float*)d_out;

    cudaFuncSetAttribute(attn_tc,
                         cudaFuncAttributeMaxDynamicSharedMemorySize, ATTN_SMEM);
    cudaFuncSetAttribute(gemm_v2<0>,
                         cudaFuncAttributeMaxDynamicSharedMemorySize, GEMM_SMEM);
    cudaFuncSetAttribute(gemm_v2<1>,
                         cudaFuncAttributeMaxDynamicSharedMemorySize, GEMM_SMEM);

    // Prepass: RNA tf32 rounding (hoisted out of the GEMM mainloops)
    const int nx4 = NT * Cn / 4;
    const int nw4 = Cn * C3 / 4;
    const int np4 = Cn * Cn / 4;
    round_tf32<0><<<(nx4 + 255) / 256, 256>>>(x, nx4);
    round_tf32<1><<<(nw4 + 255) / 256, 256>>>(w_qkv, nw4);
    round_tf32<2><<<(np4 + 255) / 256, 256>>>(w_proj, np4);

    gemm_v2<0><<<dim3(C3 / 128, NT / 256), 256, GEMM_SMEM>>>(b_qkv, nullptr);
    attn_tc<<<dim3(Tn / 64, Bn * Hn), 128, ATTN_SMEM>>>();
    gemm_v2<1><<<dim3(Cn / 128, NT / 256), 256, GEMM_SMEM>>>(b_proj, out);
}

// round 9
// speedup vs baseline: 1.1552x; 1.1552x over previous
#include <cuda_runtime.h>
#include <math.h>
#include <stdint.h>

#define Bn 4
#define Tn 2048
#define Cn 1024
#define Hn 16
#define Dn 64
#define NT (Bn * Tn)
#define C3 (3 * Cn)

__device__ float g_q[(size_t)Bn * Hn * Tn * Dn];
__device__ float g_k[(size_t)Bn * Hn * Tn * Dn];
__device__ float g_v[(size_t)Bn * Hn * Tn * Dn];
__device__ float g_y[(size_t)NT * Cn];
// pre-rounded (tf32-in-fp32) copies so the GEMM mainloop can use raw cp.async
__device__ float g_x[(size_t)NT * Cn];
__device__ float g_wqkv[(size_t)Cn * C3];
__device__ float g_wproj[(size_t)Cn * Cn];

// ---------------------------------------------------------------------------
// helpers
// ---------------------------------------------------------------------------
__device__ __forceinline__ float f2tf(float x) {
    float y;
    asm("cvt.rna.tf32.f32 %0, %1;" : "=f"(y) : "f"(x));
    return y;
}

__device__ __forceinline__ float ex2(float x) {
    float y;
    asm("ex2.approx.f32 %0, %1;" : "=f"(y) : "f"(x));
    return y;
}

__device__ __forceinline__ void mma8(float d[4], const uint32_t a[4],
                                     const uint32_t b[2], const float c[4]) {
    asm volatile(
        "mma.sync.aligned.m16n8k8.row.col.f32.tf32.tf32.f32 "
        "{%0,%1,%2,%3}, {%4,%5,%6,%7}, {%8,%9}, {%10,%11,%12,%13};"
        : "=f"(d[0]), "=f"(d[1]), "=f"(d[2]), "=f"(d[3])
        : "r"(a[0]), "r"(a[1]), "r"(a[2]), "r"(a[3]),
          "r"(b[0]), "r"(b[1]),
          "f"(c[0]), "f"(c[1]), "f"(c[2]), "f"(c[3]));
}

__device__ __forceinline__ uint32_t smem_u32(const void* p) {
    return (uint32_t)__cvta_generic_to_shared(p);
}

#define CPA16(s, gp) \
    asm volatile("cp.async.cg.shared.global [%0], [%1], 16;" :: "r"(s), "l"(gp))

// ---------------------------------------------------------------------------
// Prepass: RNA-round fp32 -> tf32-in-fp32 into device globals.
// ---------------------------------------------------------------------------
template <int WHICH>
__global__ void round_tf32(const float* __restrict__ src, int n4) {
    float* dst = (WHICH == 0) ? g_x : (WHICH == 1) ? g_wqkv : g_wproj;
    const int i = blockIdx.x * blockDim.x + threadIdx.x;
    if (i < n4) {
        float4 v = ((const float4*)src)[i];
        ((float4*)dst)[i] =
            make_float4(f2tf(v.x), f2tf(v.y), f2tf(v.z), f2tf(v.w));
    }
}

// ---------------------------------------------------------------------------
// GEMM v3 = R7 geometry (BM=128 BN=128 BK=16, 8 warps 4x2, warp tile 32x64,
// 2 CTAs/SM) + R8 pipeline (cp.async double buffer, pre-rounded inputs).
// Smem strides: As 20 (afr lanes -> 20g+q mod 32 distinct), Bs 136 (8q+g
// distinct) -> conflict-free fragment loads. 16B alignment: 20 floats = 80 B
// and 136 floats = 544 B are both multiples of 16 ✓.
// ---------------------------------------------------------------------------
#define GEMM_SMEM ((2 * 128 * 20 + 2 * 16 * 136) * 4)

template <int MODE>
__global__ __launch_bounds__(256, 2) void gemm_v3(const float* __restrict__ bias,
                                                  float* __restrict__ out) {
    const float* __restrict__ A = MODE ? (const float*)g_y : (const float*)g_x;
    const float* __restrict__ W = MODE ? (const float*)g_wproj : (const float*)g_wqkv;
    const int ldb = MODE ? Cn : C3;

    extern __shared__ float sm[];
    float* Asm = sm;                 // [2][128][20]
    float* Bsm = sm + 2 * 128 * 20;  // [2][16][136]

    const int tid = threadIdx.x;
    const int lane = tid & 31;
    const int warp = tid >> 5;
    const int warpM = warp & 3;      // 0..3 -> 32-row slab
    const int warpN = warp >> 2;     // 0..1 -> 64-col slab
    const int g = lane >> 2;
    const int q = lane & 3;

    const int rowBase = blockIdx.y * 128;
    const int colBase = blockIdx.x * 128;

    // A loader: row tid>>1, 8-float half (tid&1)
    const int aRow = tid >> 1;
    const int aOff = (tid & 1) * 8;
    // B loader: row tid>>4, 8-float col chunk
    const int bRow = tid >> 4;
    const int bCol = (tid & 15) * 8;

    const float* agp = A + (size_t)(rowBase + aRow) * Cn + aOff;
    const float* bgp = W + (size_t)bRow * ldb + colBase + bCol;

    const uint32_t asBase = smem_u32(&Asm[aRow * 20 + aOff]);
    const uint32_t bsBase = smem_u32(&Bsm[bRow * 136 + bCol]);

    float acc[2][8][4] = {};

#define ISSUE_TILE(k0, buf)                                       \
    do {                                                          \
        const float* ag = agp + (k0);                             \
        const uint32_t as = asBase + (buf) * (2560 * 4);          \
        CPA16(as,      ag);                                       \
        CPA16(as + 16, ag + 4);                                   \
        const float* bg = bgp + (size_t)(k0) * ldb;               \
        const uint32_t bs = bsBase + (buf) * (2176 * 4);          \
        CPA16(bs,      bg);                                       \
        CPA16(bs + 16, bg + 4);                                   \
        asm volatile("cp.async.commit_group;");                   \
    } while (0)

    ISSUE_TILE(0, 0);

    for (int it = 0; it < 64; it++) {
        const int buf = it & 1;
        if (it < 63) {
            ISSUE_TILE((it + 1) * 16, buf ^ 1);
            asm volatile("cp.async.wait_group 1;");
        } else {
            asm volatile("cp.async.wait_group 0;");
        }
        __syncthreads();

        const float* Ab = &Asm[buf * 2560];
        const float* Bb = &Bsm[buf * 2176];
#pragma unroll
        for (int ks = 0; ks < 16; ks += 8) {
            uint32_t afr[2][4];
#pragma unroll
            for (int mt = 0; mt < 2; mt++) {
                const int r = warpM * 32 + mt * 16 + g;
                afr[mt][0] = __float_as_uint(Ab[r * 20 + ks + q]);
                afr[mt][1] = __float_as_uint(Ab[(r + 8) * 20 + ks + q]);
                afr[mt][2] = __float_as_uint(Ab[r * 20 + ks + q + 4]);
                afr[mt][3] = __float_as_uint(Ab[(r + 8) * 20 + ks + q + 4]);
            }
#pragma unroll
            for (int nt = 0; nt < 8; nt++) {
                const int c = warpN * 64 + nt * 8 + g;
                uint32_t b2[2];
                b2[0] = __float_as_uint(Bb[(ks + q) * 136 + c]);
                b2[1] = __float_as_uint(Bb[(ks + q + 4) * 136 + c]);
#pragma unroll
                for (int mt = 0; mt < 2; mt++)
                    mma8(acc[mt][nt], afr[mt], b2, acc[mt][nt]);
            }
        }
        __syncthreads();
    }

    // Epilogue (identical to R7)
#pragma unroll
    for (int mt = 0; mt < 2; mt++) {
#pragma unroll
        for (int ih = 0; ih < 2; ih++) {
            const int m = rowBase + warpM * 32 + mt * 16 + g + ih * 8;
#pragma unroll
            for (int nt = 0; nt < 8; nt++) {
                const int n = colBase + warpN * 64 + nt * 8 + q * 2;
                const float v0 = acc[mt][nt][ih * 2 + 0] + bias[n];
                const float v1 = acc[mt][nt][ih * 2 + 1] + bias[n + 1];
                if (MODE == 1) {
                    *(float2*)&out[(size_t)m * Cn + n] = make_float2(v0, v1);
                } else {
                    const int which = n >> 10;       // 0=q 1=k 2=v
                    const int cc = n & 1023;
                    const int h = cc >> 6;
                    const int d = cc & 63;
                    const int b = m >> 11;
                    const int t = m & 2047;
                    float* dst = (which == 0) ? g_q : (which == 1) ? g_k : g_v;
                    *(float2*)&dst[(((size_t)b * Hn + h) * Tn + t) * Dn + d] =
                        make_float2(v0, v1);
                }
            }
        }
    }
#undef ISSUE_TILE
}

// ---------------------------------------------------------------------------
// Tensor-core flash attention (causal) — unchanged from R7/R8 passing version
// (epilogue writes f2tf-rounded g_y so proj can cp.async it raw).
// ---------------------------------------------------------------------------
#define LKV 72
#define ATTN_SMEM ((2 * 64 * LKV + 4 * 16 * LKV) * 4)

__global__ __launch_bounds__(128, 3) void attn_tc() {
    extern __shared__ float smf[];
    float* Kn = smf;                    // [kv][d]  stride LKV
    float* Vs = smf + 64 * LKV;         // [kv][d]  stride LKV
    float* Pw = smf + 2 * 64 * LKV;     // per-warp [16][LKV]

    const int qt = blockIdx.x;
    const int bh = blockIdx.y;
    const int b = bh >> 4;
    const int h = bh & 15;

    const int tid = threadIdx.x;
    const int w = tid >> 5;
    const int lane = tid & 31;
    const int g = lane >> 2;
    const int q = lane & 3;

    const float qscale = 0.125f * 1.44269504f;
    const float* qg = g_q + ((size_t)bh * Tn + qt * 64 + w * 16) * Dn;
    uint32_t aQ[8][4];
#pragma unroll
    for (int ks = 0; ks < 8; ks++) {
        aQ[ks][0] = __float_as_uint(f2tf(qg[g * Dn + ks * 8 + q] * qscale));
        aQ[ks][1] = __float_as_uint(f2tf(qg[(g + 8) * Dn + ks * 8 + q] * qscale));
        aQ[ks][2] = __float_as_uint(f2tf(qg[g * Dn + ks * 8 + q + 4] * qscale));
        aQ[ks][3] = __float_as_uint(f2tf(qg[(g + 8) * Dn + ks * 8 + q + 4] * qscale));
    }

    float o[8][4] = {};
    float mrow[2] = {-INFINITY, -INFINITY};
    float lrow[2] = {0.0f, 0.0f};

    const float* kg0 = g_k + (size_t)bh * Tn * Dn;
    const float* vg0 = g_v + (size_t)bh * Tn * Dn;
    float* Pme = Pw + w * 16 * LKV;

    for (int j = 0; j <= qt; j++) {
        __syncthreads();
        const float* kg = kg0 + (size_t)j * 64 * Dn;
        const float* vg = vg0 + (size_t)j * 64 * Dn;
        for (int i = tid; i < 64 * 16; i += 128) {
            const int r = i >> 4;
            const int c = (i & 15) * 4;
            float4 k4 = *(const float4*)&kg[r * Dn + c];
            *(float4*)&Kn[r * LKV + c] =
                make_float4(f2tf(k4.x), f2tf(k4.y), f2tf(k4.z), f2tf(k4.w));
            float4 v4 = *(const float4*)&vg[r * Dn + c];
            *(float4*)&Vs[r * LKV + c] =
                make_float4(f2tf(v4.x), f2tf(v4.y), f2tf(v4.z), f2tf(v4.w));
        }
        __syncthreads();

        float s[8][4] = {};
#pragma unroll
        for (int ks = 0; ks < 8; ks++) {
            uint32_t bf[8][2];
#pragma unroll
            for (int nt = 0; nt < 8; nt++) {
                bf[nt][0] = __float_as_uint(Kn[(nt * 8 + g) * LKV + ks * 8 + q]);
                bf[nt][1] = __float_as_uint(Kn[(nt * 8 + g) * LKV + ks * 8 + q + 4]);
            }
#pragma unroll
            for (int nt = 0; nt < 8; nt++)
                mma8(s[nt], aQ[ks], bf[nt], s[nt]);
        }

        if (j == qt) {
            const int lr0 = w * 16 + g;
            const int lr1 = lr0 + 8;
#pragma unroll
            for (int nt = 0; nt < 8; nt++) {
                const int lc = nt * 8 + 2 * q;
                if (lc > lr0) s[nt][0] = -INFINITY;
                if (lc + 1 > lr0) s[nt][1] = -INFINITY;
                if (lc > lr1) s[nt][2] = -INFINITY;
                if (lc + 1 > lr1) s[nt][3] = -INFINITY;
            }
        }

#pragma unroll
        for (int r = 0; r < 2; r++) {
            float mx = mrow[r];
#pragma unroll
            for (int nt = 0; nt < 8; nt++)
                mx = fmaxf(mx, fmaxf(s[nt][2 * r], s[nt][2 * r + 1]));
            mx = fmaxf(mx, __shfl_xor_sync(0xffffffffu, mx, 1));
            mx = fmaxf(mx, __shfl_xor_sync(0xffffffffu, mx, 2));
            const float alpha = ex2(mrow[r] - mx);
            float sum = 0.0f;
#pragma unroll
            for (int nt = 0; nt < 8; nt++) {
                const float p0 = ex2(s[nt][2 * r] - mx);
                const float p1 = ex2(s[nt][2 * r + 1] - mx);
                s[nt][2 * r] = p0;
                s[nt][2 * r + 1] = p1;
                sum += p0 + p1;
                o[nt][2 * r] *= alpha;
                o[nt][2 * r + 1] *= alpha;
            }
            sum += __shfl_xor_sync(0xffffffffu, sum, 1);
            sum += __shfl_xor_sync(0xffffffffu, sum, 2);
            lrow[r] = lrow[r] * alpha + sum;
            mrow[r] = mx;
        }

#pragma unroll
        for (int nt = 0; nt < 8; nt++) {
            *(float2*)&Pme[g * LKV + nt * 8 + 2 * q] =
                make_float2(f2tf(s[nt][0]), f2tf(s[nt][1]));
            *(float2*)&Pme[(g + 8) * LKV + nt * 8 + 2 * q] =
                make_float2(f2tf(s[nt][2]), f2tf(s[nt][3]));
        }
        __syncwarp();

#pragma unroll
        for (int ks = 0; ks < 8; ks++) {
            uint32_t aP[4];
            aP[0] = __float_as_uint(Pme[g * LKV + ks * 8 + q]);
            aP[1] = __float_as_uint(Pme[(g + 8) * LKV + ks * 8 + q]);
            aP[2] = __float_as_uint(Pme[g * LKV + ks * 8 + q + 4]);
            aP[3] = __float_as_uint(Pme[(g + 8) * LKV + ks * 8 + q + 4]);
            uint32_t bf[8][2];
#pragma unroll
            for (int nt = 0; nt < 8; nt++) {
                bf[nt][0] = __float_as_uint(Vs[(ks * 8 + q) * LKV + nt * 8 + g]);
                bf[nt][1] = __float_as_uint(Vs[(ks * 8 + q + 4) * LKV + nt * 8 + g]);
            }
#pragma unroll
            for (int nt = 0; nt < 8; nt++)
                mma8(o[nt], aP, bf[nt], o[nt]);
        }
    }

    const float inv0 = 1.0f / lrow[0];
    const float inv1 = 1.0f / lrow[1];
    float* yg = g_y + ((size_t)b * Tn + qt * 64 + w * 16) * Cn + h * Dn;
#pragma unroll
    for (int nt = 0; nt < 8; nt++) {
        *(float2*)&yg[(size_t)g * Cn + nt * 8 + 2 * q] =
            make_float2(f2tf(o[nt][0] * inv0), f2tf(o[nt][1] * inv0));
        *(float2*)&yg[(size_t)(g + 8) * Cn + nt * 8 + 2 * q] =
            make_float2(f2tf(o[nt][2] * inv1), f2tf(o[nt][3] * inv1));
    }
}

// ---------------------------------------------------------------------------
extern "C" void kernel_launch(void* const* d_in, const int* in_sizes, int n_in,
                              void* d_out, int out_size) {
    const float* x      = (const float*)d_in[0];
    const float* w_qkv  = (const float*)d_in[1];
    const float* b_qkv  = (const float*)d_in[2];
    const float* w_proj = (const float*)d_in[3];
    const float* b_proj = (const float*)d_in[4];
    float* out = (float*)d_out;

    cudaFuncSetAttribute(attn_tc,
                         cudaFuncAttributeMaxDynamicSharedMemorySize, ATTN_SMEM);
    cudaFuncSetAttribute(gemm_v3<0>,
                         cudaFuncAttributeMaxDynamicSharedMemorySize, GEMM_SMEM);
    cudaFuncSetAttribute(gemm_v3<1>,
                         cudaFuncAttributeMaxDynamicSharedMemorySize, GEMM_SMEM);

    const int nx4 = NT * Cn / 4;
    const int nw4 = Cn * C3 / 4;
    const int np4 = Cn * Cn / 4;
    round_tf32<0><<<(nx4 + 255) / 256, 256>>>(x, nx4);
    round_tf32<1><<<(nw4 + 255) / 256, 256>>>(w_qkv, nw4);
    round_tf32<2><<<(np4 + 255) / 256, 256>>>(w_proj, np4);

    gemm_v3<0><<<dim3(C3 / 128, NT / 128), 256, GEMM_SMEM>>>(b_qkv, nullptr);
    attn_tc<<<dim3(Tn / 64, Bn * Hn), 128, ATTN_SMEM>>>();
    gemm_v3<1><<<dim3(Cn / 128, NT / 128), 256, GEMM_SMEM>>>(b_proj, out);
}